// round 7
// baseline (speedup 1.0000x reference)
#include <cuda_runtime.h>
#include <cuda_bf16.h>

typedef unsigned long long ull;

// Transform-domain weight table:
// g_wt[ ((ds*9 + t19)*2 + kern)*16 + (u*4+v) ] = (U,U) duplicated pair
// ds = ds1*3+ds2 (9), t19 = dh1*3+dw1 (9), kern 0=k,1=k' , U = (G g G^T)[u][v]
__device__ ull g_wt[2592];

__device__ __forceinline__ ull pack2(float x, float y) {
    ull r; asm("mov.b64 %0, {%1, %2};" : "=l"(r) : "f"(x), "f"(y)); return r;
}
__device__ __forceinline__ ull fma2(ull a, ull b, ull c) {
    ull d; asm("fma.rn.f32x2 %0, %1, %2, %3;" : "=l"(d) : "l"(a), "l"(b), "l"(c)); return d;
}

__global__ void prep_kernel(const float* __restrict__ kern) {
    int i = threadIdx.x;
    if (i >= 162) return;
    int kk  = i & 1;
    int t19 = (i >> 1) % 9;
    int ds  = (i >> 1) / 9;
    int dh1 = t19 / 3, dw1 = t19 % 3;
    int ds1 = ds / 3,  ds2 = ds % 3;
    float g[3][3];
    for (int a = 0; a < 3; a++)
        for (int b = 0; b < 3; b++) {
            int idx = (kk == 0)
                ? (((((ds1*3+ds2)*3+dh1)*3+dw1)*3+a)*3+b)      // k slice over (dh2,dw2)
                : (((((ds2*3+ds1)*3+a)*3+b)*3+dh1)*3+dw1);     // k' slice
            g[a][b] = kern[idx];
        }
    // U = G g G^T,  G = [1,0,0; .5,.5,.5; .5,-.5,.5; 0,0,1]
    float t[4][3];
    for (int c = 0; c < 3; c++) {
        t[0][c] = g[0][c];
        t[1][c] = 0.5f*(g[0][c]+g[1][c]+g[2][c]);
        t[2][c] = 0.5f*(g[0][c]-g[1][c]+g[2][c]);
        t[3][c] = g[2][c];
    }
    int base = ((ds*9 + t19)*2 + kk)*16;
    for (int r = 0; r < 4; r++) {
        float U0 = t[r][0];
        float U1 = 0.5f*(t[r][0]+t[r][1]+t[r][2]);
        float U2 = 0.5f*(t[r][0]-t[r][1]+t[r][2]);
        float U3 = t[r][2];
        g_wt[base + r*4 + 0] = pack2(U0, U0);
        g_wt[base + r*4 + 1] = pack2(U1, U1);
        g_wt[base + r*4 + 2] = pack2(U2, U2);
        g_wt[base + r*4 + 3] = pack2(U3, U3);
    }
}

// ---------------------------------------------------------------------------
// Winograd F(2x2,3x3) over (h2,w2). CTA tile (h1,w1,h2,w2) = (4,4,8,8).
// 512 threads = (q=h1*4+w1: 16) x (sp: 2, so-pair) x (uv: 16).
// SMEM:
//   Tsm: transformed tiles [s 4][plane 36][uv 16][20 words(16 ij + 4 pad)]
//        = 46080 floats (184320 B); reused as M in epilogue
//   raw: one s_in halo plane set [36][10][12] = 4320 floats (17280 B)
//   Wsm: 2592 ull (20736 B)
// total 222336 B -> 1 CTA/SM.
// ---------------------------------------------------------------------------
#define T_FLOATS   46080
#define RAW_FLOATS 4320
#define SMEM_BYTES (222336)

__global__ __launch_bounds__(512, 1)
void conv_kernel(const float* __restrict__ x, float* __restrict__ out) {
    extern __shared__ float sm[];
    float* Tsm = sm;
    float* raw = sm + T_FLOATS;
    ull*   Wsm = (ull*)(sm + T_FLOATS + RAW_FLOATS);

    const int tid = threadIdx.x;
    const int bid = blockIdx.x;
    const int bw2 = bid & 3;
    const int bh2 = (bid >> 2) & 3;
    const int bw1 = (bid >> 4) & 7;
    const int bh1 = bid >> 7;

    const int H1o = bh1 * 4 - 1, W1o = bw1 * 4 - 1;
    const int H2o = bh2 * 8 - 1, W2o = bw2 * 8 - 1;

    // ---- Phase 0: weight table to smem ----
    for (int i = tid; i < 2592; i += 512) Wsm[i] = g_wt[i];

    // ---- Phase 1: per s_in, load raw halo planes then transform ----
    for (int s_in = 0; s_in < 4; s_in++) {
        // raw halo [36 planes][10][12], relu'd, zero-padded
        for (int i = tid; i < RAW_FLOATS; i += 512) {
            int a4 = i % 12;
            int a3 = (i / 12) % 10;
            int a2 = (i / 120) % 6;
            int a1 = i / 720;
            int g1 = H1o + a1, g2 = W1o + a2, g3 = H2o + a3, g4 = W2o + a4;
            float v = 0.0f;
            if (((unsigned)g1 < 32u) && ((unsigned)g2 < 32u) &&
                ((unsigned)g3 < 32u) && ((unsigned)g4 < 32u)) {
                v = fmaxf(x[(((s_in * 32 + g1) * 32 + g2) * 32 + g3) * 32 + g4], 0.0f);
            }
            raw[i] = v;
        }
        __syncthreads();
        // transform: 36 planes x 16 tiles -> V = B^T d B
        for (int t = tid; t < 576; t += 512) {
            int plane = t >> 4;
            int ij = t & 15;
            int ti = ij >> 2, tj = ij & 3;
            const float* dp = raw + plane * 120 + (2*ti) * 12 + (2*tj);
            float d[4][4];
#pragma unroll
            for (int r = 0; r < 4; r++)
#pragma unroll
                for (int c = 0; c < 4; c++) d[r][c] = dp[r*12 + c];
            // rows: B^T d
            float tr[4][4];
#pragma unroll
            for (int c = 0; c < 4; c++) {
                tr[0][c] = d[0][c] - d[2][c];
                tr[1][c] = d[1][c] + d[2][c];
                tr[2][c] = d[2][c] - d[1][c];
                tr[3][c] = d[1][c] - d[3][c];
            }
            float* Tw = Tsm + ((s_in*36 + plane)*16) * 20 + ij;
#pragma unroll
            for (int r = 0; r < 4; r++) {
                float V0 = tr[r][0] - tr[r][2];
                float V1 = tr[r][1] + tr[r][2];
                float V2 = tr[r][2] - tr[r][1];
                float V3 = tr[r][1] - tr[r][3];
                Tw[(r*4 + 0)*20] = V0;
                Tw[(r*4 + 1)*20] = V1;
                Tw[(r*4 + 2)*20] = V2;
                Tw[(r*4 + 3)*20] = V3;
            }
        }
        __syncthreads();
    }

    // ---- Phase 2: transform-domain accumulation ----
    const int uv = tid & 15;
    const int sp = (tid >> 4) & 1;
    const int q  = tid >> 5;
    const int h1 = q >> 2, w1 = q & 3;
    const int plane0 = h1 * 6 + w1;

    // acc[ipair(8)][ab(2)][kern(2)] : pair over (ij, ij+1), (k,*) NOT packed —
    // packing is over adjacent ij; ab selects so = 2*sp+ab; kern selects k/k'
    ull acc[32];
#pragma unroll
    for (int i = 0; i < 32; i++) acc[i] = 0ull;

#pragma unroll 1
    for (int s_in = 0; s_in < 4; s_in++) {
        const int s1i = s_in >> 1, s2i = s_in & 1;
        const int dsA = (s1i - sp + 1) * 3 + (s2i + 1);   // so = 2*sp   (s2o=0)
        // dsB = dsA - 1                                   // so = 2*sp+1 (s2o=1)
        const ull* WA = Wsm + dsA * 288 + uv;
        const ull* WB = WA - 288;
        const float* Ts = Tsm + ((s_in*36 + plane0)*16 + uv) * 20;
#pragma unroll
        for (int dh1 = 0; dh1 < 3; dh1++) {
#pragma unroll
            for (int dw1 = 0; dw1 < 3; dw1++) {
                const int t19 = dh1 * 3 + dw1;
                const float* Tp = Ts + (dh1*6 + dw1) * 320;   // immediate
                ull wAk  = WA[t19*32];
                ull wAt  = WA[t19*32 + 16];
                ull wBk  = WB[t19*32];
                ull wBt  = WB[t19*32 + 16];
#pragma unroll
                for (int qd = 0; qd < 4; qd++) {
                    ulonglong2 tq = *(const ulonglong2*)(Tp + qd*4);
                    const int i0 = (2*qd) * 4, i1 = (2*qd + 1) * 4;
                    acc[i0+0] = fma2(tq.x, wAk, acc[i0+0]);
                    acc[i0+1] = fma2(tq.x, wAt, acc[i0+1]);
                    acc[i0+2] = fma2(tq.x, wBk, acc[i0+2]);
                    acc[i0+3] = fma2(tq.x, wBt, acc[i0+3]);
                    acc[i1+0] = fma2(tq.y, wAk, acc[i1+0]);
                    acc[i1+1] = fma2(tq.y, wAt, acc[i1+1]);
                    acc[i1+2] = fma2(tq.y, wBk, acc[i1+2]);
                    acc[i1+3] = fma2(tq.y, wBt, acc[i1+3]);
                }
            }
        }
    }

    // ---- Phase 3: write M to smem (reuse T region) ----
    __syncthreads();
    // M[q 16][so 4][k 2][uv 16][18 words (16 ij + 2 pad)]
    float* Msm = sm;
#pragma unroll
    for (int ip = 0; ip < 8; ip++)
#pragma unroll
        for (int ab = 0; ab < 2; ab++)
#pragma unroll
            for (int k = 0; k < 2; k++) {
                int so = 2*sp + ab;
                int word = (((q*4 + so)*2 + k)*16 + uv)*18 + 2*ip;
                *(ull*)(Msm + word) = acc[ip*4 + ab*2 + k];
            }
    __syncthreads();

    // ---- Phase 4: inverse transform + sigmoid + mask + reduce ----
    {
        const int sp2 = tid & 1;
        const int ij2 = (tid >> 1) & 15;
        const int q2  = tid >> 5;
        const int ti = ij2 >> 2, tj = ij2 & 3;
        const int H1 = bh1*4 + (q2 >> 2), W1 = bw1*4 + (q2 & 3);
        const int H2 = bh2*8 + 2*ti,      W2 = bw2*8 + 2*tj;

        float part00 = 0.f, part01 = 0.f, part10 = 0.f, part11 = 0.f;
#pragma unroll
        for (int ab = 0; ab < 2; ab++) {
            int so = 2*sp2 + ab;
            float y[2][2][2];   // [k][r][c]
#pragma unroll
            for (int k = 0; k < 2; k++) {
                float m[16];
                int base = (((q2*4 + so)*2 + k)*16)*18 + ij2;
#pragma unroll
                for (int u = 0; u < 16; u++) m[u] = Msm[base + u*18];
                // A^T M A
                float p0[4], p1[4];
#pragma unroll
                for (int c = 0; c < 4; c++) {
                    p0[c] = m[c] + m[4+c] + m[8+c];
                    p1[c] = m[4+c] - m[8+c] - m[12+c];
                }
                y[k][0][0] = p0[0] + p0[1] + p0[2];
                y[k][0][1] = p0[1] - p0[2] - p0[3];
                y[k][1][0] = p1[0] + p1[1] + p1[2];
                y[k][1][1] = p1[1] - p1[2] - p1[3];
            }
            // mask per so, sum sigmoid(k) + sigmoid(k')
            const float* xs = x + so * 1048576 + ((H1*32 + W1)*32 + H2)*32 + W2;
            float2 x0 = *(const float2*)xs;
            float2 x1 = *(const float2*)(xs + 32);
            float s00 = 1.0f/(1.0f+__expf(-y[0][0][0])) + 1.0f/(1.0f+__expf(-y[1][0][0]));
            float s01 = 1.0f/(1.0f+__expf(-y[0][0][1])) + 1.0f/(1.0f+__expf(-y[1][0][1]));
            float s10 = 1.0f/(1.0f+__expf(-y[0][1][0])) + 1.0f/(1.0f+__expf(-y[1][1][0]));
            float s11 = 1.0f/(1.0f+__expf(-y[0][1][1])) + 1.0f/(1.0f+__expf(-y[1][1][1]));
            part00 += (x0.x != 0.0f) ? s00 : 0.0f;
            part01 += (x0.y != 0.0f) ? s01 : 0.0f;
            part10 += (x1.x != 0.0f) ? s10 : 0.0f;
            part11 += (x1.y != 0.0f) ? s11 : 0.0f;
        }
        // combine the two so-pairs (partner lane differs only in sp2)
        part00 += __shfl_xor_sync(0xFFFFFFFFu, part00, 1);
        part01 += __shfl_xor_sync(0xFFFFFFFFu, part01, 1);
        part10 += __shfl_xor_sync(0xFFFFFFFFu, part10, 1);
        part11 += __shfl_xor_sync(0xFFFFFFFFu, part11, 1);
        // lane sp2 writes row r = sp2
        float2 row = (sp2 == 0) ? make_float2(part00, part01)
                                : make_float2(part10, part11);
        *(float2*)(out + ((H1*32 + W1)*32 + (H2 + sp2))*32 + W2) = row;
    }
}

extern "C" void kernel_launch(void* const* d_in, const int* in_sizes, int n_in,
                              void* d_out, int out_size) {
    const float* x    = (const float*)d_in[0];   // (1,2,2,32,32,32,32)
    const float* kern = (const float*)d_in[1];   // (729,)
    float* out = (float*)d_out;                  // (1,32,32,32,32)

    prep_kernel<<<1, 192>>>(kern);

    cudaFuncSetAttribute(conv_kernel,
                         cudaFuncAttributeMaxDynamicSharedMemorySize, SMEM_BYTES);
    conv_kernel<<<1024, 512, SMEM_BYTES>>>(x, out);
}